// round 5
// baseline (speedup 1.0000x reference)
#include <cuda_runtime.h>
#include <cuda_fp16.h>

#define NN 50000
#define EE 800000
#define ET 850000   // EE + NN self loops
#define HID 96
#define NEG 0.2f
#define GN 8        // nodes per gemm block

#define SCAN_TPB 256
#define SCAN_BLOCKS ((NN + SCAN_TPB - 1) / SCAN_TPB)   // 196

// ---------------- scratch (no cudaMalloc allowed) ----------------
__device__ __half2 g_h2[NN * 48];      // h in fp16, 48 half2 per row
__device__ float g_bufA[NN * HID];
__device__ float g_bufB[NN * HID];
__device__ float g_es[NN];
__device__ float g_ed[NN];
__device__ float g_hf[NN];
__device__ float g_esf[NN];
__device__ float g_edf[NN];
__device__ int   g_cnt[NN];
__device__ int   g_rowptr[NN + 1];
__device__ int   g_fill[NN];
__device__ int   g_srcbuf[ET];
__device__ int   g_bsum[SCAN_BLOCKS];
__device__ int   g_is64;

__device__ __forceinline__ float* sel_buf(int s) {
    return (s == 1) ? g_bufA : g_bufB;
}

// ---------------- init: zero counters + dtype probe ----------------
__global__ void init_kernel(const int* __restrict__ ei32) {
    int i = blockIdx.x * blockDim.x + threadIdx.x;
    if (i < NN) g_cnt[i] = 0;
    if (blockIdx.x == 0) {
        __shared__ int nz;
        if (threadIdx.x == 0) nz = 0;
        __syncthreads();
        if (ei32[2 * threadIdx.x + 1] != 0) nz = 1;  // benign race
        __syncthreads();
        if (threadIdx.x == 0) g_is64 = (nz == 0) ? 1 : 0;
    }
}

__device__ __forceinline__ int load_idx(const void* ei, long long pos) {
    if (g_is64) return (int)((const long long*)ei)[pos];
    return ((const int*)ei)[pos];
}

// ---------------- CSR build ----------------
__global__ void hist_kernel(const void* __restrict__ ei) {
    int j = blockIdx.x * blockDim.x + threadIdx.x;
    if (j >= ET) return;
    int dst = (j < EE) ? load_idx(ei, (long long)EE + j) : (j - EE);
    atomicAdd(&g_cnt[dst], 1);
}

__global__ void bsum_kernel() {
    __shared__ int sh[SCAN_TPB];
    int t = threadIdx.x;
    int i = blockIdx.x * SCAN_TPB + t;
    sh[t] = (i < NN) ? g_cnt[i] : 0;
    __syncthreads();
#pragma unroll
    for (int off = SCAN_TPB / 2; off > 0; off >>= 1) {
        if (t < off) sh[t] += sh[t + off];
        __syncthreads();
    }
    if (t == 0) g_bsum[blockIdx.x] = sh[0];
}

__global__ void scanout_kernel() {
    __shared__ int shoff[SCAN_TPB];
    __shared__ int sh[SCAN_TPB];
    int t = threadIdx.x;
    shoff[t] = (t < blockIdx.x && t < SCAN_BLOCKS) ? g_bsum[t] : 0;
    int i = blockIdx.x * SCAN_TPB + t;
    int c = (i < NN) ? g_cnt[i] : 0;
    sh[t] = c;
    __syncthreads();
#pragma unroll
    for (int off = SCAN_TPB / 2; off > 0; off >>= 1) {
        if (t < off) shoff[t] += shoff[t + off];
        __syncthreads();
    }
#pragma unroll
    for (int off = 1; off < SCAN_TPB; off <<= 1) {
        int v = sh[t];
        int add = (t >= off) ? sh[t - off] : 0;
        __syncthreads();
        sh[t] = v + add;
        __syncthreads();
    }
    int excl = sh[t] - c + shoff[0];
    if (i < NN) {
        g_rowptr[i] = excl;
        g_fill[i]   = excl;
    }
    if (i == NN - 1) g_rowptr[NN] = ET;
}

__global__ void scatter_kernel(const void* __restrict__ ei) {
    int j = blockIdx.x * blockDim.x + threadIdx.x;
    if (j >= ET) return;
    int src, dst;
    if (j < EE) {
        src = load_idx(ei, j);
        dst = load_idx(ei, (long long)EE + j);
    } else {
        src = dst = j - EE;
    }
    int pos = atomicAdd(&g_fill[dst], 1);
    g_srcbuf[pos] = src;
}

// ---------------- fused GEMM + esed + fp16 convert ----------------
// 8 nodes per block, 96 threads (thread o = output column).
// Packed f32x2 FMA: 2 nodes per accumulator. es/ed reduced in fp32 (exact).
template <int IN>
__global__ void gemm_kernel(const float* __restrict__ x, int in_sel,
                            const float* __restrict__ W,
                            const float* __restrict__ as, const float* __restrict__ ad) {
    __shared__ __align__(16) float2 xs[IN][GN / 2];   // xs[k][pair] = (node2p, node2p+1)
    __shared__ float sred[3][GN][2];
    const float* in = (in_sel == 0) ? x : sel_buf(in_sel);
    int nb = blockIdx.x * GN;
    int o = threadIdx.x;   // 0..95
    int lane = o & 31, wrp = o >> 5;

    for (int idx = o; idx < GN * IN; idx += HID) {
        int n = idx / IN, c = idx % IN;
        float v = in[(nb + n) * IN + c];
        if (n & 1) xs[c][n >> 1].y = v; else xs[c][n >> 1].x = v;
    }
    __syncthreads();

    unsigned long long acc[GN / 2] = {0ull, 0ull, 0ull, 0ull};   // (0.f,0.f) bits
#pragma unroll 4
    for (int k = 0; k < IN; k++) {
        float w = W[k * HID + o];
        unsigned long long ww;
        asm("mov.b64 %0, {%1, %1};" : "=l"(ww) : "r"(__float_as_uint(w)));
        ulonglong2 X01 = *reinterpret_cast<const ulonglong2*>(&xs[k][0]);
        ulonglong2 X23 = *reinterpret_cast<const ulonglong2*>(&xs[k][2]);
        asm("fma.rn.f32x2 %0, %1, %2, %0;" : "+l"(acc[0]) : "l"(X01.x), "l"(ww));
        asm("fma.rn.f32x2 %0, %1, %2, %0;" : "+l"(acc[1]) : "l"(X01.y), "l"(ww));
        asm("fma.rn.f32x2 %0, %1, %2, %0;" : "+l"(acc[2]) : "l"(X23.x), "l"(ww));
        asm("fma.rn.f32x2 %0, %1, %2, %0;" : "+l"(acc[3]) : "l"(X23.y), "l"(ww));
    }

    float asv = as[o], adv = ad[o];
#pragma unroll
    for (int p = 0; p < GN / 2; p++) {
        float hx = __uint_as_float((unsigned)acc[p]);          // node 2p, col o
        float hy = __uint_as_float((unsigned)(acc[p] >> 32));  // node 2p+1, col o
        // fp16 h write: pair adjacent columns via shfl
        float nx = __shfl_down_sync(0xFFFFFFFFu, hx, 1);
        float ny = __shfl_down_sync(0xFFFFFFFFu, hy, 1);
        if (!(o & 1)) {
            g_h2[(nb + 2 * p)     * 48 + (o >> 1)] = __floats2half2_rn(hx, nx);
            g_h2[(nb + 2 * p + 1) * 48 + (o >> 1)] = __floats2half2_rn(hy, ny);
        }
        // es/ed partials (fp32, exact)
        float vsx = hx * asv, vdx = hx * adv, vsy = hy * asv, vdy = hy * adv;
#pragma unroll
        for (int off = 16; off; off >>= 1) {
            vsx += __shfl_xor_sync(0xFFFFFFFFu, vsx, off);
            vdx += __shfl_xor_sync(0xFFFFFFFFu, vdx, off);
            vsy += __shfl_xor_sync(0xFFFFFFFFu, vsy, off);
            vdy += __shfl_xor_sync(0xFFFFFFFFu, vdy, off);
        }
        if (lane == 0) {
            sred[wrp][2 * p][0]     = vsx;  sred[wrp][2 * p][1]     = vdx;
            sred[wrp][2 * p + 1][0] = vsy;  sred[wrp][2 * p + 1][1] = vdy;
        }
    }
    __syncthreads();
    if (o < GN * 2) {
        int n = o >> 1, which = o & 1;
        float v = sred[0][n][which] + sred[1][n][which] + sred[2][n][which];
        if (which == 0) g_es[nb + n] = v; else g_ed[nb + n] = v;
    }
}

// ---------------- aggregation: one warp per destination node ----------------
// Lane-parallel (src, es) gather + exp, then shfl-broadcast accumulate of fp16 h.
// Element mapping: lane -> elems (2l, 2l+1); lanes 0-15 also (64+2l, 64+2l+1).
template <bool RESID, bool FINAL>
__global__ void agg_kernel(const float* __restrict__ b, int resid_sel, int out_sel,
                           const float* __restrict__ Wf,
                           const float* __restrict__ asf,
                           const float* __restrict__ adf) {
    int node = (blockIdx.x * blockDim.x + threadIdx.x) >> 5;
    int lane = threadIdx.x & 31;
    if (node >= NN) return;
    int beg = g_rowptr[node], end = g_rowptr[node + 1];
    float edst = g_ed[node];
    int lo16 = 32 + (lane & 15);

    // chunk 0 cached in registers
    int j0 = beg + lane;
    int s0 = 0; float e0 = -1e30f;
    if (j0 < end) {
        s0 = g_srcbuf[j0];
        float e = g_es[s0] + edst;
        e0 = (e > 0.f) ? e : NEG * e;
    }
    float m = e0;
    for (int j = beg + 32 + lane; j < end; j += 32) {
        float e = g_es[g_srcbuf[j]] + edst;
        e = (e > 0.f) ? e : NEG * e;
        m = fmaxf(m, e);
    }
#pragma unroll
    for (int off = 16; off; off >>= 1)
        m = fmaxf(m, __shfl_xor_sync(0xFFFFFFFFu, m, off));

    float a00 = 0.f, a01 = 0.f, a10 = 0.f, a11 = 0.f, ssum = 0.f;
    {
        float ex = (j0 < end) ? __expf(e0 - m) : 0.f;
        ssum += ex;
        int cnt = min(32, end - beg);
        for (int k = 0; k < cnt; k++) {
            float exk = __shfl_sync(0xFFFFFFFFu, ex, k);
            int   sk  = __shfl_sync(0xFFFFFFFFu, s0, k);
            const __half2* hp = g_h2 + sk * 48;
            float2 f0 = __half22float2(hp[lane]);
            float2 f1 = __half22float2(hp[lo16]);
            a00 += exk * f0.x; a01 += exk * f0.y;
            a10 += exk * f1.x; a11 += exk * f1.y;
        }
    }
    for (int base = beg + 32; base < end; base += 32) {
        int j = base + lane;
        int s = 0; float ex = 0.f;
        if (j < end) {
            s = g_srcbuf[j];
            float e = g_es[s] + edst;
            e = (e > 0.f) ? e : NEG * e;
            ex = __expf(e - m);
        }
        ssum += ex;
        int cnt = min(32, end - base);
        for (int k = 0; k < cnt; k++) {
            float exk = __shfl_sync(0xFFFFFFFFu, ex, k);
            int   sk  = __shfl_sync(0xFFFFFFFFu, s, k);
            const __half2* hp = g_h2 + sk * 48;
            float2 f0 = __half22float2(hp[lane]);
            float2 f1 = __half22float2(hp[lo16]);
            a00 += exk * f0.x; a01 += exk * f0.y;
            a10 += exk * f1.x; a11 += exk * f1.y;
        }
    }
#pragma unroll
    for (int off = 16; off; off >>= 1)
        ssum += __shfl_xor_sync(0xFFFFFFFFu, ssum, off);
    float inv = 1.f / ssum;

    const float2* b2 = (const float2*)b;
    float2 bl = b2[lane], bh = b2[lo16];
    float o00 = a00 * inv + bl.x, o01 = a01 * inv + bl.y;
    float o10 = a10 * inv + bh.x, o11 = a11 * inv + bh.y;
    if (RESID) {
        const float2* rp = (const float2*)(sel_buf(resid_sel) + node * HID);
        float2 r0 = rp[lane], r1 = rp[lo16];
        o00 += r0.x; o01 += r0.y; o10 += r1.x; o11 += r1.y;
    }
    o00 = fmaxf(o00, 0.f); o01 = fmaxf(o01, 0.f);
    o10 = fmaxf(o10, 0.f); o11 = fmaxf(o11, 0.f);
    if (FINAL) {
        const float2* wf2 = (const float2*)Wf;
        float2 w0 = wf2[lane], w1 = wf2[lo16];
        float v = o00 * w0.x + o01 * w0.y;
        if (lane < 16) v += o10 * w1.x + o11 * w1.y;
#pragma unroll
        for (int off = 16; off; off >>= 1)
            v += __shfl_xor_sync(0xFFFFFFFFu, v, off);
        if (lane == 0) {
            g_hf[node]  = v;
            g_esf[node] = v * asf[0];
            g_edf[node] = v * adf[0];
        }
    } else {
        float2* op = (float2*)(sel_buf(out_sel) + node * HID);
        op[lane] = make_float2(o00, o01);
        if (lane < 16) op[lo16] = make_float2(o10, o11);
    }
}

// ---------------- final aggregation (out dim = 1) ----------------
__global__ void fagg_kernel(const float* __restrict__ bf, float* __restrict__ out) {
    int node = (blockIdx.x * blockDim.x + threadIdx.x) >> 5;
    int lane = threadIdx.x & 31;
    if (node >= NN) return;
    int beg = g_rowptr[node], end = g_rowptr[node + 1];
    float edst = g_edf[node];

    float m = -1e30f;
    for (int j = beg + lane; j < end; j += 32) {
        float e = g_esf[g_srcbuf[j]] + edst;
        e = (e > 0.f) ? e : NEG * e;
        m = fmaxf(m, e);
    }
#pragma unroll
    for (int off = 16; off; off >>= 1)
        m = fmaxf(m, __shfl_xor_sync(0xFFFFFFFFu, m, off));

    float ssum = 0.f, wsum = 0.f;
    for (int j = beg + lane; j < end; j += 32) {
        int s = g_srcbuf[j];
        float e = g_esf[s] + edst;
        e = (e > 0.f) ? e : NEG * e;
        float ex = __expf(e - m);
        ssum += ex;
        wsum += ex * g_hf[s];
    }
#pragma unroll
    for (int off = 16; off; off >>= 1) {
        ssum += __shfl_xor_sync(0xFFFFFFFFu, ssum, off);
        wsum += __shfl_xor_sync(0xFFFFFFFFu, wsum, off);
    }
    if (lane == 0) out[node] = wsum / ssum + bf[0];
}

// ---------------- launch ----------------
extern "C" void kernel_launch(void* const* d_in, const int* in_sizes, int n_in,
                              void* d_out, int out_size) {
    const float* x   = (const float*)d_in[0];
    const void*  ei  = d_in[1];
    const float* W0  = (const float*)d_in[3];
    const float* as0 = (const float*)d_in[4];
    const float* ad0 = (const float*)d_in[5];
    const float* b0  = (const float*)d_in[6];
    const float* W1  = (const float*)d_in[7];
    const float* as1 = (const float*)d_in[8];
    const float* ad1 = (const float*)d_in[9];
    const float* b1  = (const float*)d_in[10];
    const float* W2  = (const float*)d_in[11];
    const float* as2 = (const float*)d_in[12];
    const float* ad2 = (const float*)d_in[13];
    const float* b2  = (const float*)d_in[14];
    const float* Wf  = (const float*)d_in[15];
    const float* asf = (const float*)d_in[16];
    const float* adf = (const float*)d_in[17];
    const float* bf  = (const float*)d_in[18];
    float* out = (float*)d_out;

    const int TPB = 256;
    const int edge_blocks = (ET + TPB - 1) / TPB;
    const int node_warp_blocks = (NN * 32 + TPB - 1) / TPB;   // 1 warp per node

    // CSR build
    init_kernel<<<SCAN_BLOCKS, SCAN_TPB>>>((const int*)ei);
    hist_kernel<<<edge_blocks, TPB>>>(ei);
    bsum_kernel<<<SCAN_BLOCKS, SCAN_TPB>>>();
    scanout_kernel<<<SCAN_BLOCKS, SCAN_TPB>>>();
    scatter_kernel<<<edge_blocks, TPB>>>(ei);

    // Layer 0: 32 -> 96, no residual.  out -> bufA
    gemm_kernel<32><<<NN / GN, HID>>>(x, 0, W0, as0, ad0);
    agg_kernel<false, false><<<node_warp_blocks, TPB>>>(b0, 0, 1, nullptr, nullptr, nullptr);

    // Layer 1: 96 -> 96, residual(bufA).  out -> bufB
    gemm_kernel<HID><<<NN / GN, HID>>>(nullptr, 1, W1, as1, ad1);
    agg_kernel<true, false><<<node_warp_blocks, TPB>>>(b1, 1, 2, nullptr, nullptr, nullptr);

    // Layer 2: 96 -> 96, residual(bufB), fused final 96->1 projection
    gemm_kernel<HID><<<NN / GN, HID>>>(nullptr, 2, W2, as2, ad2);
    agg_kernel<true, true><<<node_warp_blocks, TPB>>>(b2, 2, 0, Wf, asf, adf);

    // Final layer aggregation (dim 1)
    fagg_kernel<<<node_warp_blocks, TPB>>>(bf, out);
}

// round 6
// speedup vs baseline: 1.0022x; 1.0022x over previous
#include <cuda_runtime.h>
#include <cuda_fp16.h>

#define NN 50000
#define EE 800000
#define ET 850000   // EE + NN self loops
#define HID 96
#define NEG 0.2f
#define GN 8        // nodes per gemm block

#define SCAN_TPB 256
#define SCAN_BLOCKS ((NN + SCAN_TPB - 1) / SCAN_TPB)   // 196

// ---------------- scratch (no cudaMalloc allowed) ----------------
__device__ __half2 g_h2[NN * 48];      // h in fp16, 48 half2 per row
__device__ float g_bufA[NN * HID];
__device__ float g_bufB[NN * HID];
__device__ float g_es[NN];
__device__ float g_ed[NN];
__device__ float g_hf[NN];
__device__ float g_esf[NN];
__device__ float g_edf[NN];
__device__ int   g_cnt[NN];
__device__ int   g_rowptr[NN + 1];
__device__ int   g_fill[NN];
__device__ int   g_srcbuf[ET];
__device__ int   g_bsum[SCAN_BLOCKS];
__device__ int   g_is64;

__device__ __forceinline__ float* sel_buf(int s) {
    return (s == 1) ? g_bufA : g_bufB;
}

// ---------------- init: zero counters + dtype probe ----------------
__global__ void init_kernel(const int* __restrict__ ei32) {
    int i = blockIdx.x * blockDim.x + threadIdx.x;
    if (i < NN) g_cnt[i] = 0;
    if (blockIdx.x == 0) {
        __shared__ int nz;
        if (threadIdx.x == 0) nz = 0;
        __syncthreads();
        if (ei32[2 * threadIdx.x + 1] != 0) nz = 1;  // benign race
        __syncthreads();
        if (threadIdx.x == 0) g_is64 = (nz == 0) ? 1 : 0;
    }
}

__device__ __forceinline__ int load_idx(const void* ei, long long pos) {
    if (g_is64) return (int)((const long long*)ei)[pos];
    return ((const int*)ei)[pos];
}

// ---------------- CSR build ----------------
__global__ void hist_kernel(const void* __restrict__ ei) {
    int j = blockIdx.x * blockDim.x + threadIdx.x;
    if (j >= ET) return;
    int dst = (j < EE) ? load_idx(ei, (long long)EE + j) : (j - EE);
    atomicAdd(&g_cnt[dst], 1);
}

__global__ void bsum_kernel() {
    __shared__ int sh[SCAN_TPB];
    int t = threadIdx.x;
    int i = blockIdx.x * SCAN_TPB + t;
    sh[t] = (i < NN) ? g_cnt[i] : 0;
    __syncthreads();
#pragma unroll
    for (int off = SCAN_TPB / 2; off > 0; off >>= 1) {
        if (t < off) sh[t] += sh[t + off];
        __syncthreads();
    }
    if (t == 0) g_bsum[blockIdx.x] = sh[0];
}

__global__ void scanout_kernel() {
    __shared__ int shoff[SCAN_TPB];
    __shared__ int sh[SCAN_TPB];
    int t = threadIdx.x;
    shoff[t] = (t < blockIdx.x && t < SCAN_BLOCKS) ? g_bsum[t] : 0;
    int i = blockIdx.x * SCAN_TPB + t;
    int c = (i < NN) ? g_cnt[i] : 0;
    sh[t] = c;
    __syncthreads();
#pragma unroll
    for (int off = SCAN_TPB / 2; off > 0; off >>= 1) {
        if (t < off) shoff[t] += shoff[t + off];
        __syncthreads();
    }
#pragma unroll
    for (int off = 1; off < SCAN_TPB; off <<= 1) {
        int v = sh[t];
        int add = (t >= off) ? sh[t - off] : 0;
        __syncthreads();
        sh[t] = v + add;
        __syncthreads();
    }
    int excl = sh[t] - c + shoff[0];
    if (i < NN) {
        g_rowptr[i] = excl;
        g_fill[i]   = excl;
    }
    if (i == NN - 1) g_rowptr[NN] = ET;
}

__global__ void scatter_kernel(const void* __restrict__ ei) {
    int j = blockIdx.x * blockDim.x + threadIdx.x;
    if (j >= ET) return;
    int src, dst;
    if (j < EE) {
        src = load_idx(ei, j);
        dst = load_idx(ei, (long long)EE + j);
    } else {
        src = dst = j - EE;
    }
    int pos = atomicAdd(&g_fill[dst], 1);
    g_srcbuf[pos] = src;
}

// ---------------- fused GEMM + esed + fp16 convert ----------------
// 8 nodes per block, 96 threads (thread o = output column).
// Packed f32x2 FMA: 2 nodes per accumulator. es/ed reduced in fp32 (exact).
template <int IN>
__global__ void gemm_kernel(const float* __restrict__ x, int in_sel,
                            const float* __restrict__ W,
                            const float* __restrict__ as, const float* __restrict__ ad) {
    __shared__ __align__(16) float2 xs[IN][GN / 2];   // xs[k][pair] = (node2p, node2p+1)
    __shared__ float sred[3][GN][2];
    const float* in = (in_sel == 0) ? x : sel_buf(in_sel);
    int nb = blockIdx.x * GN;
    int o = threadIdx.x;   // 0..95
    int lane = o & 31, wrp = o >> 5;

    for (int idx = o; idx < GN * IN; idx += HID) {
        int n = idx / IN, c = idx % IN;
        float v = in[(nb + n) * IN + c];
        if (n & 1) xs[c][n >> 1].y = v; else xs[c][n >> 1].x = v;
    }
    __syncthreads();

    unsigned long long acc[GN / 2] = {0ull, 0ull, 0ull, 0ull};   // (0.f,0.f) bits
#pragma unroll 4
    for (int k = 0; k < IN; k++) {
        float w = W[k * HID + o];
        unsigned long long ww;
        asm("mov.b64 %0, {%1, %1};" : "=l"(ww) : "r"(__float_as_uint(w)));
        ulonglong2 X01 = *reinterpret_cast<const ulonglong2*>(&xs[k][0]);
        ulonglong2 X23 = *reinterpret_cast<const ulonglong2*>(&xs[k][2]);
        asm("fma.rn.f32x2 %0, %1, %2, %0;" : "+l"(acc[0]) : "l"(X01.x), "l"(ww));
        asm("fma.rn.f32x2 %0, %1, %2, %0;" : "+l"(acc[1]) : "l"(X01.y), "l"(ww));
        asm("fma.rn.f32x2 %0, %1, %2, %0;" : "+l"(acc[2]) : "l"(X23.x), "l"(ww));
        asm("fma.rn.f32x2 %0, %1, %2, %0;" : "+l"(acc[3]) : "l"(X23.y), "l"(ww));
    }

    float asv = as[o], adv = ad[o];
#pragma unroll
    for (int p = 0; p < GN / 2; p++) {
        float hx = __uint_as_float((unsigned)acc[p]);          // node 2p, col o
        float hy = __uint_as_float((unsigned)(acc[p] >> 32));  // node 2p+1, col o
        // fp16 h write: pair adjacent columns via shfl
        float nx = __shfl_down_sync(0xFFFFFFFFu, hx, 1);
        float ny = __shfl_down_sync(0xFFFFFFFFu, hy, 1);
        if (!(o & 1)) {
            g_h2[(nb + 2 * p)     * 48 + (o >> 1)] = __floats2half2_rn(hx, nx);
            g_h2[(nb + 2 * p + 1) * 48 + (o >> 1)] = __floats2half2_rn(hy, ny);
        }
        // es/ed partials (fp32, exact)
        float vsx = hx * asv, vdx = hx * adv, vsy = hy * asv, vdy = hy * adv;
#pragma unroll
        for (int off = 16; off; off >>= 1) {
            vsx += __shfl_xor_sync(0xFFFFFFFFu, vsx, off);
            vdx += __shfl_xor_sync(0xFFFFFFFFu, vdx, off);
            vsy += __shfl_xor_sync(0xFFFFFFFFu, vsy, off);
            vdy += __shfl_xor_sync(0xFFFFFFFFu, vdy, off);
        }
        if (lane == 0) {
            sred[wrp][2 * p][0]     = vsx;  sred[wrp][2 * p][1]     = vdx;
            sred[wrp][2 * p + 1][0] = vsy;  sred[wrp][2 * p + 1][1] = vdy;
        }
    }
    __syncthreads();
    if (o < GN * 2) {
        int n = o >> 1, which = o & 1;
        float v = sred[0][n][which] + sred[1][n][which] + sred[2][n][which];
        if (which == 0) g_es[nb + n] = v; else g_ed[nb + n] = v;
    }
}

// ---------------- aggregation: one warp per destination node ----------------
// Pass A: lane-parallel segment max. Pass B: serial per-edge broadcast loop
// (no shuffles in hot loop), fp16 h gather: 2 LDG/lane/edge.
// Element mapping: lane -> elems (2l, 2l+1); elems (64+2m, 64+2m+1) via lo16.
template <bool RESID, bool FINAL>
__global__ void agg_kernel(const float* __restrict__ b, int resid_sel, int out_sel,
                           const float* __restrict__ Wf,
                           const float* __restrict__ asf,
                           const float* __restrict__ adf) {
    int node = (blockIdx.x * blockDim.x + threadIdx.x) >> 5;
    int lane = threadIdx.x & 31;
    if (node >= NN) return;
    int beg = g_rowptr[node], end = g_rowptr[node + 1];
    float edst = g_ed[node];
    int lo16 = 32 + (lane & 15);

    float m = -1e30f;
    for (int j = beg + lane; j < end; j += 32) {
        float e = g_es[g_srcbuf[j]] + edst;
        e = (e > 0.f) ? e : NEG * e;
        m = fmaxf(m, e);
    }
#pragma unroll
    for (int off = 16; off; off >>= 1)
        m = fmaxf(m, __shfl_xor_sync(0xFFFFFFFFu, m, off));

    float a00 = 0.f, a01 = 0.f, a10 = 0.f, a11 = 0.f, ssum = 0.f;
#pragma unroll 4
    for (int j = beg; j < end; j++) {
        int s = g_srcbuf[j];                 // broadcast load
        float e = g_es[s] + edst;            // broadcast load
        e = (e > 0.f) ? e : NEG * e;
        float ex = __expf(e - m);
        const __half2* hp = g_h2 + s * 48;
        float2 f0 = __half22float2(hp[lane]);
        float2 f1 = __half22float2(hp[lo16]);
        ssum += ex;
        a00 += ex * f0.x; a01 += ex * f0.y;
        a10 += ex * f1.x; a11 += ex * f1.y;
    }
    float inv = 1.f / ssum;

    const float2* b2 = (const float2*)b;
    float2 bl = b2[lane], bh = b2[lo16];
    float o00 = a00 * inv + bl.x, o01 = a01 * inv + bl.y;
    float o10 = a10 * inv + bh.x, o11 = a11 * inv + bh.y;
    if (RESID) {
        const float2* rp = (const float2*)(sel_buf(resid_sel) + node * HID);
        float2 r0 = rp[lane], r1 = rp[lo16];
        o00 += r0.x; o01 += r0.y; o10 += r1.x; o11 += r1.y;
    }
    o00 = fmaxf(o00, 0.f); o01 = fmaxf(o01, 0.f);
    o10 = fmaxf(o10, 0.f); o11 = fmaxf(o11, 0.f);
    if (FINAL) {
        const float2* wf2 = (const float2*)Wf;
        float2 w0 = wf2[lane], w1 = wf2[lo16];
        float v = o00 * w0.x + o01 * w0.y;
        if (lane < 16) v += o10 * w1.x + o11 * w1.y;
#pragma unroll
        for (int off = 16; off; off >>= 1)
            v += __shfl_xor_sync(0xFFFFFFFFu, v, off);
        if (lane == 0) {
            g_hf[node]  = v;
            g_esf[node] = v * asf[0];
            g_edf[node] = v * adf[0];
        }
    } else {
        float2* op = (float2*)(sel_buf(out_sel) + node * HID);
        op[lane] = make_float2(o00, o01);
        if (lane < 16) op[lo16] = make_float2(o10, o11);
    }
}

// ---------------- final aggregation (out dim = 1) ----------------
__global__ void fagg_kernel(const float* __restrict__ bf, float* __restrict__ out) {
    int node = (blockIdx.x * blockDim.x + threadIdx.x) >> 5;
    int lane = threadIdx.x & 31;
    if (node >= NN) return;
    int beg = g_rowptr[node], end = g_rowptr[node + 1];
    float edst = g_edf[node];

    float m = -1e30f;
    for (int j = beg + lane; j < end; j += 32) {
        float e = g_esf[g_srcbuf[j]] + edst;
        e = (e > 0.f) ? e : NEG * e;
        m = fmaxf(m, e);
    }
#pragma unroll
    for (int off = 16; off; off >>= 1)
        m = fmaxf(m, __shfl_xor_sync(0xFFFFFFFFu, m, off));

    float ssum = 0.f, wsum = 0.f;
    for (int j = beg + lane; j < end; j += 32) {
        int s = g_srcbuf[j];
        float e = g_esf[s] + edst;
        e = (e > 0.f) ? e : NEG * e;
        float ex = __expf(e - m);
        ssum += ex;
        wsum += ex * g_hf[s];
    }
#pragma unroll
    for (int off = 16; off; off >>= 1) {
        ssum += __shfl_xor_sync(0xFFFFFFFFu, ssum, off);
        wsum += __shfl_xor_sync(0xFFFFFFFFu, wsum, off);
    }
    if (lane == 0) out[node] = wsum / ssum + bf[0];
}

// ---------------- launch ----------------
extern "C" void kernel_launch(void* const* d_in, const int* in_sizes, int n_in,
                              void* d_out, int out_size) {
    const float* x   = (const float*)d_in[0];
    const void*  ei  = d_in[1];
    const float* W0  = (const float*)d_in[3];
    const float* as0 = (const float*)d_in[4];
    const float* ad0 = (const float*)d_in[5];
    const float* b0  = (const float*)d_in[6];
    const float* W1  = (const float*)d_in[7];
    const float* as1 = (const float*)d_in[8];
    const float* ad1 = (const float*)d_in[9];
    const float* b1  = (const float*)d_in[10];
    const float* W2  = (const float*)d_in[11];
    const float* as2 = (const float*)d_in[12];
    const float* ad2 = (const float*)d_in[13];
    const float* b2  = (const float*)d_in[14];
    const float* Wf  = (const float*)d_in[15];
    const float* asf = (const float*)d_in[16];
    const float* adf = (const float*)d_in[17];
    const float* bf  = (const float*)d_in[18];
    float* out = (float*)d_out;

    const int TPB = 256;
    const int edge_blocks = (ET + TPB - 1) / TPB;
    const int node_warp_blocks = (NN * 32 + TPB - 1) / TPB;   // 1 warp per node

    // CSR build
    init_kernel<<<SCAN_BLOCKS, SCAN_TPB>>>((const int*)ei);
    hist_kernel<<<edge_blocks, TPB>>>(ei);
    bsum_kernel<<<SCAN_BLOCKS, SCAN_TPB>>>();
    scanout_kernel<<<SCAN_BLOCKS, SCAN_TPB>>>();
    scatter_kernel<<<edge_blocks, TPB>>>(ei);

    // Layer 0: 32 -> 96, no residual.  out -> bufA
    gemm_kernel<32><<<NN / GN, HID>>>(x, 0, W0, as0, ad0);
    agg_kernel<false, false><<<node_warp_blocks, TPB>>>(b0, 0, 1, nullptr, nullptr, nullptr);

    // Layer 1: 96 -> 96, residual(bufA).  out -> bufB
    gemm_kernel<HID><<<NN / GN, HID>>>(nullptr, 1, W1, as1, ad1);
    agg_kernel<true, false><<<node_warp_blocks, TPB>>>(b1, 1, 2, nullptr, nullptr, nullptr);

    // Layer 2: 96 -> 96, residual(bufB), fused final 96->1 projection
    gemm_kernel<HID><<<NN / GN, HID>>>(nullptr, 2, W2, as2, ad2);
    agg_kernel<true, true><<<node_warp_blocks, TPB>>>(b2, 2, 0, Wf, asf, adf);

    // Final layer aggregation (dim 1)
    fagg_kernel<<<node_warp_blocks, TPB>>>(bf, out);
}